// round 6
// baseline (speedup 1.0000x reference)
#include <cuda_runtime.h>
#include <cuda_bf16.h>
#include <cstdint>

#define B_ 4
#define N_ 4096
#define D_ 1024
#define H_ 4
#define DH_ 256
#define FF_ 4096
#define ROWS_ (B_*N_)

typedef __nv_bfloat16 bf16;

// ---------------- scratch ----------------
__device__ float g_q[ROWS_*D_];     // q f32 / unused later
__device__ float g_k[ROWS_*D_];     // k f32
__device__ float g_v[ROWS_*D_];     // v f32 / out1 f32
__device__ bf16 g_ah[ROWS_*D_],  g_al[ROWS_*D_];    // LN1-h / attn-out / LN2-h split
__device__ bf16 g_qh[ROWS_*D_],  g_ql[ROWS_*D_];    // q split / out2 split
__device__ bf16 g_ffh[ROWS_*FF_], g_ffl[ROWS_*FF_]; // ffn hidden split
__device__ bf16 g_kTh[B_*H_*DH_*N_], g_kTl[B_*H_*DH_*N_];
__device__ bf16 g_vTh[B_*H_*DH_*N_], g_vTl[B_*H_*DH_*N_];
__device__ bf16 g_cTh[B_*H_*DH_*DH_], g_cTl[B_*H_*DH_*DH_];
__device__ bf16 g_wq_hi[D_*D_], g_wq_lo[D_*D_], g_wk_hi[D_*D_], g_wk_lo[D_*D_];
__device__ bf16 g_wv_hi[D_*D_], g_wv_lo[D_*D_], g_wo_hi[D_*D_], g_wo_lo[D_*D_];
__device__ bf16 g_wd_hi[D_*D_], g_wd_lo[D_*D_];
__device__ bf16 g_f1_hi[D_*FF_], g_f1_lo[D_*FF_];
__device__ bf16 g_f2_hi[FF_*D_], g_f2_lo[FF_*D_];

// ---------------- helpers ----------------
__device__ __forceinline__ uint32_t smem_u32(const void* p) {
    uint32_t a;
    asm("{ .reg .u64 t; cvta.to.shared.u64 t, %1; cvt.u32.u64 %0, t; }" : "=r"(a) : "l"(p));
    return a;
}
__device__ __forceinline__ void cp_async16(uint32_t s, const void* g) {
    asm volatile("cp.async.cg.shared.global [%0], [%1], 16;\n" :: "r"(s), "l"(g));
}
__device__ __forceinline__ void cp_commit() { asm volatile("cp.async.commit_group;\n"); }
__device__ __forceinline__ void cp_wait1()  { asm volatile("cp.async.wait_group 1;\n"); }
__device__ __forceinline__ void cp_wait0()  { asm volatile("cp.async.wait_group 0;\n"); }

__device__ __forceinline__ void ldsm4(uint32_t* r, uint32_t a) {
    asm volatile("ldmatrix.sync.aligned.m8n8.x4.shared.b16 {%0,%1,%2,%3}, [%4];"
                 : "=r"(r[0]), "=r"(r[1]), "=r"(r[2]), "=r"(r[3]) : "r"(a));
}
__device__ __forceinline__ void mma16816(float* d, const uint32_t* a, const uint32_t* b) {
    asm volatile(
        "mma.sync.aligned.m16n8k16.row.col.f32.bf16.bf16.f32 "
        "{%0,%1,%2,%3}, {%4,%5,%6,%7}, {%8,%9}, {%0,%1,%2,%3};"
        : "+f"(d[0]), "+f"(d[1]), "+f"(d[2]), "+f"(d[3])
        : "r"(a[0]), "r"(a[1]), "r"(a[2]), "r"(a[3]), "r"(b[0]), "r"(b[1]));
}
__device__ __forceinline__ float gelu_f(float x) {
    float t = tanhf(0.7978845608028654f * (x + 0.044715f * x * x * x));
    return 0.5f * x * (1.0f + t);
}
__device__ __forceinline__ uint32_t pack2(float a, float b) {
    unsigned short ha = __bfloat16_as_ushort(__float2bfloat16_rn(a));
    unsigned short hb = __bfloat16_as_ushort(__float2bfloat16_rn(b));
    return ((uint32_t)hb << 16) | ha;
}
__device__ __forceinline__ void split1(float v, bf16& h, bf16& l) {
    h = __float2bfloat16_rn(v);
    l = __float2bfloat16_rn(v - __bfloat162float(h));
}

// ---------------------------------------------------------------------------
// gemm_mma: C[M][Nc] = A @ B^T where A = (Ah+Al)[M][lda-strided, K cols] bf16,
// B = (Bh+Bl)[Nc][K] K-major bf16. 3-pass split, fp32 accum.
// CTA 128x128, BK=32, 8 warps (4m x 2n), warp 32x64, cp.async double buffer.
// epi: 0 none, 1 +bias, 2 +bias+resid, 3 gelu(bias+). If Chi: write split only.
// ---------------------------------------------------------------------------
#define GS_BYTES 81920
#define LDS_ 40

__global__ void __launch_bounds__(256, 1) gemm_mma(
    const bf16* __restrict__ Ah, const bf16* __restrict__ Al,
    const bf16* __restrict__ Bh, const bf16* __restrict__ Bl,
    float* __restrict__ Cf, bf16* __restrict__ Chi, bf16* __restrict__ Clo,
    const float* __restrict__ bias, const float* __restrict__ resid,
    int K, int lda, int ldc, int epi,
    int bm, long aO, long aI, long bO, long bI, long cO, long cI)
{
    extern __shared__ char smem[];
    uint32_t sb = smem_u32(smem);
    if (bm) {
        int z = blockIdx.z; long o = z / bm, ii = z % bm;
        Ah += o * aO + ii * aI; Al += o * aO + ii * aI;
        Bh += o * bO + ii * bI; Bl += o * bO + ii * bI;
        long co = o * cO + ii * cI;
        if (Cf) Cf += co;
        if (Chi) { Chi += co; Clo += co; }
        if (resid) resid += co;
    }
    int tid = threadIdx.x, lane = tid & 31, wid = tid >> 5;
    int wm = wid >> 1, wn = wid & 1;
    long rowBlk = (long)blockIdx.y * 128;
    int  colBlk = blockIdx.x * 128;

    float acc[2][8][4];
    #pragma unroll
    for (int i = 0; i < 2; i++)
        #pragma unroll
        for (int j = 0; j < 8; j++)
            #pragma unroll
            for (int r = 0; r < 4; r++) acc[i][j][r] = 0.f;

    // load coords: 512 16B-chunks per array per stage / 256 threads = 2
    int r0 = tid >> 2,        c0 = (tid & 3) * 8;
    int r1 = (tid + 256) >> 2, c1 = ((tid + 256) & 3) * 8;

    int S = K >> 5;
    int buf = 0;

    #define LOADSTAGE(s, bp) do { \
        long k0 = (long)(s) * 32; \
        uint32_t d0 = sb + (bp) * 10240 + (r0 * LDS_ + c0) * 2; \
        uint32_t d1 = sb + (bp) * 10240 + (r1 * LDS_ + c1) * 2; \
        cp_async16(d0,         Ah + (rowBlk + r0) * lda + k0 + c0); \
        cp_async16(d1,         Ah + (rowBlk + r1) * lda + k0 + c1); \
        cp_async16(d0 + 20480, Al + (rowBlk + r0) * lda + k0 + c0); \
        cp_async16(d1 + 20480, Al + (rowBlk + r1) * lda + k0 + c1); \
        cp_async16(d0 + 40960, Bh + (long)(colBlk + r0) * K + k0 + c0); \
        cp_async16(d1 + 40960, Bh + (long)(colBlk + r1) * K + k0 + c1); \
        cp_async16(d0 + 61440, Bl + (long)(colBlk + r0) * K + k0 + c0); \
        cp_async16(d1 + 61440, Bl + (long)(colBlk + r1) * K + k0 + c1); \
    } while (0)

    LOADSTAGE(0, 0);
    cp_commit();

    int la = lane & 15, lha = (lane >> 4) * 8;           // A ldsm row / col-half
    int brr = ((lane >> 4) & 1) * 8 + (lane & 7);        // B ldsm row comp
    int bcc = ((lane >> 3) & 1) * 8;                     // B ldsm col-half

    for (int s = 0; s < S; s++) {
        if (s + 1 < S) { LOADSTAGE(s + 1, buf ^ 1); cp_commit(); cp_wait1(); }
        else cp_wait0();
        __syncthreads();

        uint32_t sA  = sb + buf * 10240;
        uint32_t sAl = sA + 20480;
        uint32_t sBh = sA + 40960;
        uint32_t sBl = sA + 61440;

        #pragma unroll
        for (int h = 0; h < 32; h += 16) {
            uint32_t ah0[4], ah1[4], al0[4], al1[4];
            uint32_t ra0 = ((wm * 32 + la) * LDS_ + h + lha) * 2;
            uint32_t ra1 = ((wm * 32 + 16 + la) * LDS_ + h + lha) * 2;
            ldsm4(ah0, sA + ra0);
            ldsm4(ah1, sA + ra1);
            ldsm4(al0, sAl + ra0);
            ldsm4(al1, sAl + ra1);
            uint32_t bh[4][4], bl[4][4];
            #pragma unroll
            for (int pn = 0; pn < 4; pn++) {
                uint32_t ro = ((wn * 64 + pn * 16 + brr) * LDS_ + h + bcc) * 2;
                ldsm4(bh[pn], sBh + ro);
                ldsm4(bl[pn], sBl + ro);
            }
            #pragma unroll
            for (int nt = 0; nt < 8; nt++) {
                uint32_t* B2h = &bh[nt >> 1][(nt & 1) * 2];
                uint32_t* B2l = &bl[nt >> 1][(nt & 1) * 2];
                mma16816(acc[0][nt], ah0, B2h);
                mma16816(acc[1][nt], ah1, B2h);
                mma16816(acc[0][nt], ah0, B2l);
                mma16816(acc[1][nt], ah1, B2l);
                mma16816(acc[0][nt], al0, B2h);
                mma16816(acc[1][nt], al1, B2h);
            }
        }
        __syncthreads();
        buf ^= 1;
    }

    // epilogue
    int g = lane >> 2, c2 = (lane & 3) * 2;
    #pragma unroll
    for (int mt = 0; mt < 2; mt++) {
        #pragma unroll
        for (int nt = 0; nt < 8; nt++) {
            long rr0 = rowBlk + wm * 32 + mt * 16 + g;
            int  cc  = colBlk + wn * 64 + nt * 8 + c2;
            float2 v0 = make_float2(acc[mt][nt][0], acc[mt][nt][1]);
            float2 v1 = make_float2(acc[mt][nt][2], acc[mt][nt][3]);
            if (epi) {
                float2 bv = *(const float2*)(bias + cc);
                v0.x += bv.x; v0.y += bv.y; v1.x += bv.x; v1.y += bv.y;
            }
            if (epi == 2) {
                float2 q0 = *(const float2*)(resid + rr0 * ldc + cc);
                float2 q1 = *(const float2*)(resid + (rr0 + 8) * ldc + cc);
                v0.x += q0.x; v0.y += q0.y; v1.x += q1.x; v1.y += q1.y;
            }
            if (epi == 3) {
                v0.x = gelu_f(v0.x); v0.y = gelu_f(v0.y);
                v1.x = gelu_f(v1.x); v1.y = gelu_f(v1.y);
            }
            if (Chi) {
                bf16 h0, l0, h1, l1, h2, l2, h3, l3;
                split1(v0.x, h0, l0); split1(v0.y, h1, l1);
                split1(v1.x, h2, l2); split1(v1.y, h3, l3);
                *(uint32_t*)(Chi + rr0 * ldc + cc) =
                    ((uint32_t)__bfloat16_as_ushort(h1) << 16) | __bfloat16_as_ushort(h0);
                *(uint32_t*)(Clo + rr0 * ldc + cc) =
                    ((uint32_t)__bfloat16_as_ushort(l1) << 16) | __bfloat16_as_ushort(l0);
                *(uint32_t*)(Chi + (rr0 + 8) * ldc + cc) =
                    ((uint32_t)__bfloat16_as_ushort(h3) << 16) | __bfloat16_as_ushort(h2);
                *(uint32_t*)(Clo + (rr0 + 8) * ldc + cc) =
                    ((uint32_t)__bfloat16_as_ushort(l3) << 16) | __bfloat16_as_ushort(l2);
            } else {
                *(float2*)(Cf + rr0 * ldc + cc) = v0;
                *(float2*)(Cf + (rr0 + 8) * ldc + cc) = v1;
            }
        }
    }
}

// ---------------- pointwise kernels ----------------
__global__ void __launch_bounds__(256) layernorm_split(
    const float* __restrict__ x, const float* __restrict__ g,
    const float* __restrict__ b, bf16* __restrict__ oh, bf16* __restrict__ ol)
{
    long row = blockIdx.x; int t = threadIdx.x;
    float4 v = ((const float4*)(x + row * D_))[t];
    float s = v.x+v.y+v.z+v.w, ss = v.x*v.x+v.y*v.y+v.z*v.z+v.w*v.w;
    #pragma unroll
    for (int o = 16; o; o >>= 1) {
        s += __shfl_xor_sync(~0u, s, o); ss += __shfl_xor_sync(~0u, ss, o);
    }
    __shared__ float shs[8], shss[8], shmu, shrs;
    int w = t >> 5, l = t & 31;
    if (l == 0) { shs[w] = s; shss[w] = ss; }
    __syncthreads();
    if (t == 0) {
        float S = 0, SS = 0;
        #pragma unroll
        for (int i = 0; i < 8; i++) { S += shs[i]; SS += shss[i]; }
        float mu = S / D_;
        shmu = mu; shrs = rsqrtf(SS / D_ - mu * mu + 1e-5f);
    }
    __syncthreads();
    float mu = shmu, rs = shrs;
    float4 gg = ((const float4*)g)[t], bb = ((const float4*)b)[t];
    float o0 = (v.x-mu)*rs*gg.x+bb.x, o1 = (v.y-mu)*rs*gg.y+bb.y;
    float o2 = (v.z-mu)*rs*gg.z+bb.z, o3 = (v.w-mu)*rs*gg.w+bb.w;
    bf16 h0,l0,h1,l1,h2,l2,h3,l3;
    split1(o0,h0,l0); split1(o1,h1,l1); split1(o2,h2,l2); split1(o3,h3,l3);
    uint2 hv = make_uint2(((uint32_t)__bfloat16_as_ushort(h1)<<16)|__bfloat16_as_ushort(h0),
                          ((uint32_t)__bfloat16_as_ushort(h3)<<16)|__bfloat16_as_ushort(h2));
    uint2 lv = make_uint2(((uint32_t)__bfloat16_as_ushort(l1)<<16)|__bfloat16_as_ushort(l0),
                          ((uint32_t)__bfloat16_as_ushort(l3)<<16)|__bfloat16_as_ushort(l2));
    *(uint2*)(oh + row * D_ + t * 4) = hv;
    *(uint2*)(ol + row * D_ + t * 4) = lv;
}

__global__ void __launch_bounds__(256) softmax_q_split(
    const float* __restrict__ q, bf16* __restrict__ qh, bf16* __restrict__ ql)
{
    int warp = threadIdx.x >> 5, lane = threadIdx.x & 31;
    long row = (long)blockIdx.x * 8 + warp;
    const float* p = q + row * DH_;
    float v[8], mx = -1e30f;
    #pragma unroll
    for (int i = 0; i < 8; i++) { v[i] = p[lane + i*32] * 0.25f; mx = fmaxf(mx, v[i]); }
    #pragma unroll
    for (int o = 16; o; o >>= 1) mx = fmaxf(mx, __shfl_xor_sync(~0u, mx, o));
    float s = 0.f;
    #pragma unroll
    for (int i = 0; i < 8; i++) { v[i] = expf(v[i] - mx); s += v[i]; }
    #pragma unroll
    for (int o = 16; o; o >>= 1) s += __shfl_xor_sync(~0u, s, o);
    float inv = 1.f / s;
    #pragma unroll
    for (int i = 0; i < 8; i++) {
        bf16 h, l; split1(v[i] * inv, h, l);
        qh[row * DH_ + lane + i*32] = h;
        ql[row * DH_ + lane + i*32] = l;
    }
}

__global__ void softmax_k(float* __restrict__ k)
{
    int b = blockIdx.y >> 2, h = blockIdx.y & 3;
    float* base = k + (long)b*N_*D_ + h*DH_ + blockIdx.x*32 + threadIdx.x;
    __shared__ float red[8][32];
    int tx = threadIdx.x, ty = threadIdx.y;
    float mx = -1e30f;
    for (int n = ty; n < N_; n += 8) mx = fmaxf(mx, base[(long)n * D_]);
    red[ty][tx] = mx; __syncthreads();
    #pragma unroll
    for (int i = 0; i < 8; i++) mx = fmaxf(mx, red[i][tx]);
    mx *= 0.25f; __syncthreads();
    float s = 0.f;
    for (int n = ty; n < N_; n += 8) s += expf(base[(long)n * D_] * 0.25f - mx);
    red[ty][tx] = s; __syncthreads();
    s = 0.f;
    #pragma unroll
    for (int i = 0; i < 8; i++) s += red[i][tx];
    float inv = 1.f / s;
    for (int n = ty; n < N_; n += 8)
        base[(long)n * D_] = expf(base[(long)n * D_] * 0.25f - mx) * inv;
}

// W f32 [K][Nc] -> hi/lo bf16 [Nc][K]
__global__ void wsplit_t(const float* __restrict__ W, bf16* __restrict__ hi,
                         bf16* __restrict__ lo, int K, int Nc)
{
    __shared__ float t[32][33];
    int k0 = blockIdx.y*32, n0 = blockIdx.x*32, tx = threadIdx.x, ty = threadIdx.y;
    #pragma unroll
    for (int i = 0; i < 32; i += 8) t[ty+i][tx] = W[(long)(k0+ty+i)*Nc + n0+tx];
    __syncthreads();
    #pragma unroll
    for (int i = 0; i < 32; i += 8) {
        bf16 h, l; split1(t[tx][ty+i], h, l);
        long o = (long)(n0+ty+i)*K + k0+tx;
        hi[o] = h; lo[o] = l;
    }
}
// src [b,n,h*DH+d] f32 -> hi/lo [z][d][n]
__global__ void trans_split(const float* __restrict__ src_, bf16* __restrict__ hi,
                            bf16* __restrict__ lo)
{
    __shared__ float t[32][33];
    int z = blockIdx.z, b = z >> 2, h = z & 3;
    int n0 = blockIdx.x*32, d0 = blockIdx.y*32, tx = threadIdx.x, ty = threadIdx.y;
    const float* src = src_ + (long)b*N_*D_ + h*DH_;
    #pragma unroll
    for (int i = 0; i < 32; i += 8) t[ty+i][tx] = src[(long)(n0+ty+i)*D_ + d0+tx];
    __syncthreads();
    long base = (long)z*DH_*N_;
    #pragma unroll
    for (int i = 0; i < 32; i += 8) {
        bf16 hh, ll; split1(t[tx][ty+i], hh, ll);
        long o = base + (long)(d0+ty+i)*N_ + n0+tx;
        hi[o] = hh; lo[o] = ll;
    }
}

// ---------------------------------------------------------------------------
extern "C" void kernel_launch(void* const* d_in, const int* in_sizes, int n_in,
                              void* d_out, int out_size)
{
    const float* x     = (const float*)d_in[0];
    const float* ln1_g = (const float*)d_in[1];
    const float* ln1_b = (const float*)d_in[2];
    const float* wq = (const float*)d_in[3];
    const float* wk = (const float*)d_in[4];
    const float* wv = (const float*)d_in[5];
    const float* wo = (const float*)d_in[6];
    const float* bo = (const float*)d_in[7];
    const float* ln2_g = (const float*)d_in[8];
    const float* ln2_b = (const float*)d_in[9];
    const float* w_ff1 = (const float*)d_in[10];
    const float* b_ff1 = (const float*)d_in[11];
    const float* w_ff2 = (const float*)d_in[12];
    const float* b_ff2 = (const float*)d_in[13];
    const float* w_d = (const float*)d_in[14];
    const float* b_d = (const float*)d_in[15];
    float* out = (float*)d_out;

    cudaFuncSetAttribute(gemm_mma, cudaFuncAttributeMaxDynamicSharedMemorySize, GS_BYTES);

    float *qb, *kb, *vb;
    bf16 *ah,*al,*qh,*ql,*ffh,*ffl,*kTh,*kTl,*vTh,*vTl,*cTh,*cTl;
    bf16 *WQh,*WQl,*WKh,*WKl,*WVh,*WVl,*WOh,*WOl,*WDh,*WDl,*F1h,*F1l,*F2h,*F2l;
    cudaGetSymbolAddress((void**)&qb, g_q);
    cudaGetSymbolAddress((void**)&kb, g_k);
    cudaGetSymbolAddress((void**)&vb, g_v);
    cudaGetSymbolAddress((void**)&ah, g_ah);   cudaGetSymbolAddress((void**)&al, g_al);
    cudaGetSymbolAddress((void**)&qh, g_qh);   cudaGetSymbolAddress((void**)&ql, g_ql);
    cudaGetSymbolAddress((void**)&ffh, g_ffh); cudaGetSymbolAddress((void**)&ffl, g_ffl);
    cudaGetSymbolAddress((void**)&kTh, g_kTh); cudaGetSymbolAddress((void**)&kTl, g_kTl);
    cudaGetSymbolAddress((void**)&vTh, g_vTh); cudaGetSymbolAddress((void**)&vTl, g_vTl);
    cudaGetSymbolAddress((void**)&cTh, g_cTh); cudaGetSymbolAddress((void**)&cTl, g_cTl);
    cudaGetSymbolAddress((void**)&WQh, g_wq_hi); cudaGetSymbolAddress((void**)&WQl, g_wq_lo);
    cudaGetSymbolAddress((void**)&WKh, g_wk_hi); cudaGetSymbolAddress((void**)&WKl, g_wk_lo);
    cudaGetSymbolAddress((void**)&WVh, g_wv_hi); cudaGetSymbolAddress((void**)&WVl, g_wv_lo);
    cudaGetSymbolAddress((void**)&WOh, g_wo_hi); cudaGetSymbolAddress((void**)&WOl, g_wo_lo);
    cudaGetSymbolAddress((void**)&WDh, g_wd_hi); cudaGetSymbolAddress((void**)&WDl, g_wd_lo);
    cudaGetSymbolAddress((void**)&F1h, g_f1_hi); cudaGetSymbolAddress((void**)&F1l, g_f1_lo);
    cudaGetSymbolAddress((void**)&F2h, g_f2_hi); cudaGetSymbolAddress((void**)&F2l, g_f2_lo);

    dim3 tb(32, 8);
    wsplit_t<<<dim3(D_/32, D_/32), tb>>>(wq, WQh, WQl, D_, D_);
    wsplit_t<<<dim3(D_/32, D_/32), tb>>>(wk, WKh, WKl, D_, D_);
    wsplit_t<<<dim3(D_/32, D_/32), tb>>>(wv, WVh, WVl, D_, D_);
    wsplit_t<<<dim3(D_/32, D_/32), tb>>>(wo, WOh, WOl, D_, D_);
    wsplit_t<<<dim3(D_/32, D_/32), tb>>>(w_d, WDh, WDl, D_, D_);
    wsplit_t<<<dim3(FF_/32, D_/32), tb>>>(w_ff1, F1h, F1l, D_, FF_);
    wsplit_t<<<dim3(D_/32, FF_/32), tb>>>(w_ff2, F2h, F2l, FF_, D_);

    // 1) LN1 -> split
    layernorm_split<<<ROWS_, 256>>>(x, ln1_g, ln1_b, ah, al);

    // 2) q,k,v projections (f32 outputs)
    dim3 g1(D_/128, ROWS_/128, 1);
    gemm_mma<<<g1, 256, GS_BYTES>>>(ah, al, WQh, WQl, qb, 0, 0, 0, 0,
                                    D_, D_, D_, 0, 0,0,0,0,0,0,0);
    gemm_mma<<<g1, 256, GS_BYTES>>>(ah, al, WKh, WKl, kb, 0, 0, 0, 0,
                                    D_, D_, D_, 0, 0,0,0,0,0,0,0);
    gemm_mma<<<g1, 256, GS_BYTES>>>(ah, al, WVh, WVl, vb, 0, 0, 0, 0,
                                    D_, D_, D_, 0, 0,0,0,0,0,0,0);

    // 3) feature maps
    softmax_q_split<<<ROWS_*H_/8, 256>>>(qb, qh, ql);
    softmax_k<<<dim3(DH_/32, B_*H_), tb>>>(kb);

    // 4) transpose+split k, v -> [z][d][n]
    trans_split<<<dim3(N_/32, DH_/32, B_*H_), tb>>>(kb, kTh, kTl);
    trans_split<<<dim3(N_/32, DH_/32, B_*H_), tb>>>(vb, vTh, vTl);

    // 5) cT[z][e][d] = sum_n vT[e][n] * kT[d][n]  (split output)
    gemm_mma<<<dim3(DH_/128, DH_/128, B_*H_), 256, GS_BYTES>>>(
        vTh, vTl, kTh, kTl, 0, cTh, cTl, 0, 0,
        N_, N_, DH_, 0,
        1, (long)DH_*N_, 0, (long)DH_*N_, 0, (long)DH_*DH_, 0);

    // 6) attn[b,n,h,:] = q @ cT^T (split output -> ah/al)
    gemm_mma<<<dim3(DH_/128, N_/128, B_*H_), 256, GS_BYTES>>>(
        qh, ql, cTh, cTl, 0, ah, al, 0, 0,
        DH_, D_, D_, 0,
        H_, (long)N_*D_, (long)DH_, (long)H_*DH_*DH_, (long)DH_*DH_,
        (long)N_*D_, (long)DH_);

    // 7) out1 = x + attn @ wo + bo -> vb (f32)
    gemm_mma<<<g1, 256, GS_BYTES>>>(ah, al, WOh, WOl, vb, 0, 0, bo, x,
                                    D_, D_, D_, 2, 0,0,0,0,0,0,0);

    // 8) LN2 -> split (ah/al reuse)
    layernorm_split<<<ROWS_, 256>>>(vb, ln2_g, ln2_b, ah, al);

    // 9) ff = gelu(h @ w_ff1 + b1) -> split ffh/ffl
    gemm_mma<<<dim3(FF_/128, ROWS_/128, 1), 256, GS_BYTES>>>(
        ah, al, F1h, F1l, 0, ffh, ffl, b_ff1, 0,
        D_, D_, FF_, 3, 0,0,0,0,0,0,0);

    // 10) out2 = out1 + ff @ w_ff2 + b2 -> split qh/ql
    gemm_mma<<<g1, 256, GS_BYTES>>>(ffh, ffl, F2h, F2l, 0, qh, ql, b_ff2, vb,
                                    FF_, FF_, D_, 2, 0,0,0,0,0,0,0);

    // 11) out = out2 @ w_d + b_d (f32)
    gemm_mma<<<g1, 256, GS_BYTES>>>(qh, ql, WDh, WDl, out, 0, 0, b_d, 0,
                                    D_, D_, D_, 1, 0,0,0,0,0,0,0);
}

// round 8
// speedup vs baseline: 1.0305x; 1.0305x over previous
#include <cuda_runtime.h>
#include <cuda_bf16.h>
#include <cstdint>

#define B_ 4
#define N_ 4096
#define D_ 1024
#define H_ 4
#define DH_ 256
#define FF_ 4096
#define ROWS_ (B_*N_)
#define CTXE_ (B_*H_*DH_*DH_)

typedef __nv_bfloat16 bf16;

// ---------------- scratch ----------------
__device__ float g_q[ROWS_*D_];
__device__ float g_k[ROWS_*D_];
__device__ float g_v[ROWS_*D_];
__device__ float g_cpart[8*CTXE_];                  // ctx split-K partials
__device__ bf16 g_ah[ROWS_*D_],  g_al[ROWS_*D_];
__device__ bf16 g_qh[ROWS_*D_],  g_ql[ROWS_*D_];
__device__ bf16 g_ffh[ROWS_*FF_], g_ffl[ROWS_*FF_];
__device__ bf16 g_kTh[B_*H_*DH_*N_], g_kTl[B_*H_*DH_*N_];
__device__ bf16 g_vTh[B_*H_*DH_*N_], g_vTl[B_*H_*DH_*N_];
__device__ bf16 g_cTh[CTXE_], g_cTl[CTXE_];
__device__ bf16 g_wq_hi[D_*D_], g_wq_lo[D_*D_], g_wk_hi[D_*D_], g_wk_lo[D_*D_];
__device__ bf16 g_wv_hi[D_*D_], g_wv_lo[D_*D_], g_wo_hi[D_*D_], g_wo_lo[D_*D_];
__device__ bf16 g_wd_hi[D_*D_], g_wd_lo[D_*D_];
__device__ bf16 g_f1_hi[D_*FF_], g_f1_lo[D_*FF_];
__device__ bf16 g_f2_hi[FF_*D_], g_f2_lo[FF_*D_];

// ---------------- helpers ----------------
__device__ __forceinline__ uint32_t smem_u32(const void* p) {
    uint32_t a;
    asm("{ .reg .u64 t; cvta.to.shared.u64 t, %1; cvt.u32.u64 %0, t; }" : "=r"(a) : "l"(p));
    return a;
}
__device__ __forceinline__ void cp_async16(uint32_t s, const void* g) {
    asm volatile("cp.async.cg.shared.global [%0], [%1], 16;\n" :: "r"(s), "l"(g));
}
__device__ __forceinline__ void cp_commit() { asm volatile("cp.async.commit_group;\n"); }
__device__ __forceinline__ void cp_wait2()  { asm volatile("cp.async.wait_group 2;\n"); }
__device__ __forceinline__ void cp_wait1()  { asm volatile("cp.async.wait_group 1;\n"); }
__device__ __forceinline__ void cp_wait0()  { asm volatile("cp.async.wait_group 0;\n"); }
__device__ __forceinline__ void ldsm4(uint32_t* r, uint32_t a) {
    asm volatile("ldmatrix.sync.aligned.m8n8.x4.shared.b16 {%0,%1,%2,%3}, [%4];"
                 : "=r"(r[0]), "=r"(r[1]), "=r"(r[2]), "=r"(r[3]) : "r"(a));
}
__device__ __forceinline__ void mma16816(float* d, const uint32_t* a, const uint32_t* b) {
    asm volatile(
        "mma.sync.aligned.m16n8k16.row.col.f32.bf16.bf16.f32 "
        "{%0,%1,%2,%3}, {%4,%5,%6,%7}, {%8,%9}, {%0,%1,%2,%3};"
        : "+f"(d[0]), "+f"(d[1]), "+f"(d[2]), "+f"(d[3])
        : "r"(a[0]), "r"(a[1]), "r"(a[2]), "r"(a[3]), "r"(b[0]), "r"(b[1]));
}
__device__ __forceinline__ float gelu_f(float x) {
    float t = tanhf(0.7978845608028654f * (x + 0.044715f * x * x * x));
    return 0.5f * x * (1.0f + t);
}
__device__ __forceinline__ void split1(float v, bf16& h, bf16& l) {
    h = __float2bfloat16_rn(v);
    l = __float2bfloat16_rn(v - __bfloat162float(h));
}
__device__ __forceinline__ uint32_t packbf(bf16 a, bf16 b) {
    return ((uint32_t)__bfloat16_as_ushort(b) << 16) | __bfloat16_as_ushort(a);
}

// ---------------------------------------------------------------------------
// gemm_mma: C[M][Nc] = (Ah+Al)[M][K] @ (Bh+Bl)[Nc][K]^T  3-pass, fp32 acc.
// CTA 128x256, BK=32, 3-stage cp.async, 8 warps (2m x 4n), warp 64x64.
// epi: 0 none, 1 +bias, 2 +bias+resid, 3 gelu(bias+). Chi!=0 -> split output.
// ---------------------------------------------------------------------------
#define LDS_ 40
#define STG_ 61440
#define GS_BYTES (3*STG_)

__global__ void __launch_bounds__(256, 1) gemm_mma(
    const bf16* __restrict__ Ah, const bf16* __restrict__ Al,
    const bf16* __restrict__ Bh, const bf16* __restrict__ Bl,
    float* __restrict__ Cf, bf16* __restrict__ Chi, bf16* __restrict__ Clo,
    const float* __restrict__ bias, const float* __restrict__ resid,
    int K, int lda, int ldc, int epi,
    int bm, long aO, long aI, long bO, long bI, long cO, long cI)
{
    extern __shared__ char smem[];
    uint32_t sb = smem_u32(smem);
    if (bm) {
        int z = blockIdx.z; long o = z / bm, ii = z % bm;
        Ah += o * aO + ii * aI; Al += o * aO + ii * aI;
        Bh += o * bO + ii * bI; Bl += o * bO + ii * bI;
        long co = o * cO + ii * cI;
        if (Cf) Cf += co;
        if (Chi) { Chi += co; Clo += co; }
        if (resid) resid += co;
    }
    int tid = threadIdx.x, lane = tid & 31, wid = tid >> 5;
    int wm = wid >> 2, wn = wid & 3;
    long rowBlk = (long)blockIdx.y * 128;
    int  colBlk = blockIdx.x * 256;

    float acc[4][8][4];
    #pragma unroll
    for (int i = 0; i < 4; i++)
        #pragma unroll
        for (int j = 0; j < 8; j++)
            #pragma unroll
            for (int r = 0; r < 4; r++) acc[i][j][r] = 0.f;

    int ar = tid >> 2, ac = (tid & 3) * 8;       // A: 512 chunks, 2/thread
    int S = K >> 5;

    #define LOADSTAGE(s) do { \
        long k0 = (long)(s) * 32; \
        uint32_t st = sb + ((s) % 3) * STG_; \
        uint32_t dA0 = st + (ar * LDS_ + ac) * 2; \
        uint32_t dA1 = st + ((ar + 64) * LDS_ + ac) * 2; \
        cp_async16(dA0,         Ah + (rowBlk + ar) * lda + k0 + ac); \
        cp_async16(dA1,         Ah + (rowBlk + ar + 64) * lda + k0 + ac); \
        cp_async16(dA0 + 10240, Al + (rowBlk + ar) * lda + k0 + ac); \
        cp_async16(dA1 + 10240, Al + (rowBlk + ar + 64) * lda + k0 + ac); \
        _Pragma("unroll") \
        for (int ib = 0; ib < 4; ib++) { \
            int rb = ar + ib * 64; \
            uint32_t dB = st + 20480 + (rb * LDS_ + ac) * 2; \
            cp_async16(dB,         Bh + (long)(colBlk + rb) * K + k0 + ac); \
            cp_async16(dB + 20480, Bl + (long)(colBlk + rb) * K + k0 + ac); \
        } \
    } while (0)

    LOADSTAGE(0); cp_commit();
    LOADSTAGE(1); cp_commit();

    int la = lane & 15, lha = (lane >> 4) * 8;
    int brr = ((lane >> 4) & 1) * 8 + (lane & 7);
    int bcc = ((lane >> 3) & 1) * 8;

    for (int s = 0; s < S; s++) {
        if (s + 2 < S) { LOADSTAGE(s + 2); cp_commit(); cp_wait2(); }
        else if (s + 1 < S) cp_wait1();
        else cp_wait0();
        __syncthreads();

        uint32_t st  = sb + (s % 3) * STG_;
        uint32_t sAl = st + 10240, sBh = st + 20480, sBl = st + 40960;

        #pragma unroll
        for (int h = 0; h < 32; h += 16) {
            uint32_t ah[4][4], al[4][4];
            #pragma unroll
            for (int mt = 0; mt < 4; mt++) {
                uint32_t ra = ((wm * 64 + mt * 16 + la) * LDS_ + h + lha) * 2;
                ldsm4(ah[mt], st + ra);
                ldsm4(al[mt], sAl + ra);
            }
            #pragma unroll
            for (int nc = 0; nc < 4; nc++) {
                uint32_t bh[4], bl[4];
                uint32_t rb = ((wn * 64 + nc * 16 + brr) * LDS_ + h + bcc) * 2;
                ldsm4(bh, sBh + rb);
                ldsm4(bl, sBl + rb);
                #pragma unroll
                for (int mt = 0; mt < 4; mt++) {
                    #pragma unroll
                    for (int half = 0; half < 2; half++) {
                        float* a4 = acc[mt][nc * 2 + half];
                        mma16816(a4, ah[mt], &bh[half * 2]);
                        mma16816(a4, ah[mt], &bl[half * 2]);
                        mma16816(a4, al[mt], &bh[half * 2]);
                    }
                }
            }
        }
        __syncthreads();
    }

    // epilogue
    int g = lane >> 2, c2 = (lane & 3) * 2;
    #pragma unroll
    for (int mt = 0; mt < 4; mt++) {
        #pragma unroll
        for (int nt = 0; nt < 8; nt++) {
            long rr0 = rowBlk + wm * 64 + mt * 16 + g;
            int  cc  = colBlk + wn * 64 + nt * 8 + c2;
            float2 v0 = make_float2(acc[mt][nt][0], acc[mt][nt][1]);
            float2 v1 = make_float2(acc[mt][nt][2], acc[mt][nt][3]);
            if (epi) {
                float2 bv = *(const float2*)(bias + cc);
                v0.x += bv.x; v0.y += bv.y; v1.x += bv.x; v1.y += bv.y;
            }
            if (epi == 2) {
                float2 q0 = *(const float2*)(resid + rr0 * ldc + cc);
                float2 q1 = *(const float2*)(resid + (rr0 + 8) * ldc + cc);
                v0.x += q0.x; v0.y += q0.y; v1.x += q1.x; v1.y += q1.y;
            }
            if (epi == 3) {
                v0.x = gelu_f(v0.x); v0.y = gelu_f(v0.y);
                v1.x = gelu_f(v1.x); v1.y = gelu_f(v1.y);
            }
            if (Chi) {
                bf16 h0,l0,h1,l1,h2,l2,h3,l3;
                split1(v0.x,h0,l0); split1(v0.y,h1,l1);
                split1(v1.x,h2,l2); split1(v1.y,h3,l3);
                *(uint32_t*)(Chi + rr0 * ldc + cc)       = packbf(h0, h1);
                *(uint32_t*)(Clo + rr0 * ldc + cc)       = packbf(l0, l1);
                *(uint32_t*)(Chi + (rr0 + 8) * ldc + cc) = packbf(h2, h3);
                *(uint32_t*)(Clo + (rr0 + 8) * ldc + cc) = packbf(l2, l3);
            } else {
                *(float2*)(Cf + rr0 * ldc + cc) = v0;
                *(float2*)(Cf + (rr0 + 8) * ldc + cc) = v1;
            }
        }
    }
}

// ---------------- pointwise kernels ----------------
__global__ void __launch_bounds__(256) layernorm_split(
    const float* __restrict__ x, const float* __restrict__ g,
    const float* __restrict__ b, bf16* __restrict__ oh, bf16* __restrict__ ol)
{
    long row = blockIdx.x; int t = threadIdx.x;
    float4 v = ((const float4*)(x + row * D_))[t];
    float s = v.x+v.y+v.z+v.w, ss = v.x*v.x+v.y*v.y+v.z*v.z+v.w*v.w;
    #pragma unroll
    for (int o = 16; o; o >>= 1) {
        s += __shfl_xor_sync(~0u, s, o); ss += __shfl_xor_sync(~0u, ss, o);
    }
    __shared__ float shs[8], shss[8], shmu, shrs;
    int w = t >> 5, l = t & 31;
    if (l == 0) { shs[w] = s; shss[w] = ss; }
    __syncthreads();
    if (t == 0) {
        float S = 0, SS = 0;
        #pragma unroll
        for (int i = 0; i < 8; i++) { S += shs[i]; SS += shss[i]; }
        float mu = S / D_;
        shmu = mu; shrs = rsqrtf(SS / D_ - mu * mu + 1e-5f);
    }
    __syncthreads();
    float mu = shmu, rs = shrs;
    float4 gg = ((const float4*)g)[t], bb = ((const float4*)b)[t];
    float o0 = (v.x-mu)*rs*gg.x+bb.x, o1 = (v.y-mu)*rs*gg.y+bb.y;
    float o2 = (v.z-mu)*rs*gg.z+bb.z, o3 = (v.w-mu)*rs*gg.w+bb.w;
    bf16 h0,l0,h1,l1,h2,l2,h3,l3;
    split1(o0,h0,l0); split1(o1,h1,l1); split1(o2,h2,l2); split1(o3,h3,l3);
    *(uint2*)(oh + row * D_ + t*4) = make_uint2(packbf(h0,h1), packbf(h2,h3));
    *(uint2*)(ol + row * D_ + t*4) = make_uint2(packbf(l0,l1), packbf(l2,l3));
}

__global__ void __launch_bounds__(256) softmax_q_split(
    const float* __restrict__ q, bf16* __restrict__ qh, bf16* __restrict__ ql)
{
    int warp = threadIdx.x >> 5, lane = threadIdx.x & 31;
    long row = (long)blockIdx.x * 8 + warp;
    const float* p = q + row * DH_;
    float v[8], mx = -1e30f;
    #pragma unroll
    for (int i = 0; i < 8; i++) { v[i] = p[lane + i*32] * 0.25f; mx = fmaxf(mx, v[i]); }
    #pragma unroll
    for (int o = 16; o; o >>= 1) mx = fmaxf(mx, __shfl_xor_sync(~0u, mx, o));
    float s = 0.f;
    #pragma unroll
    for (int i = 0; i < 8; i++) { v[i] = expf(v[i] - mx); s += v[i]; }
    #pragma unroll
    for (int o = 16; o; o >>= 1) s += __shfl_xor_sync(~0u, s, o);
    float inv = 1.f / s;
    #pragma unroll
    for (int i = 0; i < 8; i++) {
        bf16 h, l; split1(v[i] * inv, h, l);
        qh[row * DH_ + lane + i*32] = h;
        ql[row * DH_ + lane + i*32] = l;
    }
}

__global__ void softmax_k(float* __restrict__ k)
{
    int b = blockIdx.y >> 2, h = blockIdx.y & 3;
    float* base = k + (long)b*N_*D_ + h*DH_ + blockIdx.x*32 + threadIdx.x;
    __shared__ float red[8][32];
    int tx = threadIdx.x, ty = threadIdx.y;
    float mx = -1e30f;
    for (int n = ty; n < N_; n += 8) mx = fmaxf(mx, base[(long)n * D_]);
    red[ty][tx] = mx; __syncthreads();
    #pragma unroll
    for (int i = 0; i < 8; i++) mx = fmaxf(mx, red[i][tx]);
    mx *= 0.25f; __syncthreads();
    float s = 0.f;
    for (int n = ty; n < N_; n += 8) s += expf(base[(long)n * D_] * 0.25f - mx);
    red[ty][tx] = s; __syncthreads();
    s = 0.f;
    #pragma unroll
    for (int i = 0; i < 8; i++) s += red[i][tx];
    float inv = 1.f / s;
    for (int n = ty; n < N_; n += 8)
        base[(long)n * D_] = expf(base[(long)n * D_] * 0.25f - mx) * inv;
}

__global__ void wsplit_t(const float* __restrict__ W, bf16* __restrict__ hi,
                         bf16* __restrict__ lo, int K, int Nc)
{
    __shared__ float t[32][33];
    int k0 = blockIdx.y*32, n0 = blockIdx.x*32, tx = threadIdx.x, ty = threadIdx.y;
    #pragma unroll
    for (int i = 0; i < 32; i += 8) t[ty+i][tx] = W[(long)(k0+ty+i)*Nc + n0+tx];
    __syncthreads();
    #pragma unroll
    for (int i = 0; i < 32; i += 8) {
        bf16 h, l; split1(t[tx][ty+i], h, l);
        long o = (long)(n0+ty+i)*K + k0+tx;
        hi[o] = h; lo[o] = l;
    }
}
__global__ void trans_split(const float* __restrict__ src_, bf16* __restrict__ hi,
                            bf16* __restrict__ lo)
{
    __shared__ float t[32][33];
    int z = blockIdx.z, b = z >> 2, h = z & 3;
    int n0 = blockIdx.x*32, d0 = blockIdx.y*32, tx = threadIdx.x, ty = threadIdx.y;
    const float* src = src_ + (long)b*N_*D_ + h*DH_;
    #pragma unroll
    for (int i = 0; i < 32; i += 8) t[ty+i][tx] = src[(long)(n0+ty+i)*D_ + d0+tx];
    __syncthreads();
    long base = (long)z*DH_*N_;
    #pragma unroll
    for (int i = 0; i < 32; i += 8) {
        bf16 hh, ll; split1(t[tx][ty+i], hh, ll);
        long o = base + (long)(d0+ty+i)*N_ + n0+tx;
        hi[o] = hh; lo[o] = ll;
    }
}
// sum 8 split-K partials (fixed order -> deterministic), split to hi/lo
__global__ void reduce_split(const float* __restrict__ part,
                             bf16* __restrict__ hi, bf16* __restrict__ lo)
{
    int i = blockIdx.x * 256 + threadIdx.x;
    if (i < CTXE_) {
        float s = 0.f;
        #pragma unroll
        for (int j = 0; j < 8; j++) s += part[(long)j * CTXE_ + i];
        bf16 h, l; split1(s, h, l);
        hi[i] = h; lo[i] = l;
    }
}

// ---------------------------------------------------------------------------
extern "C" void kernel_launch(void* const* d_in, const int* in_sizes, int n_in,
                              void* d_out, int out_size)
{
    const float* x     = (const float*)d_in[0];
    const float* ln1_g = (const float*)d_in[1];
    const float* ln1_b = (const float*)d_in[2];
    const float* wq = (const float*)d_in[3];
    const float* wk = (const float*)d_in[4];
    const float* wv = (const float*)d_in[5];
    const float* wo = (const float*)d_in[6];
    const float* bo = (const float*)d_in[7];
    const float* ln2_g = (const float*)d_in[8];
    const float* ln2_b = (const float*)d_in[9];
    const float* w_ff1 = (const float*)d_in[10];
    const float* b_ff1 = (const float*)d_in[11];
    const float* w_ff2 = (const float*)d_in[12];
    const float* b_ff2 = (const float*)d_in[13];
    const float* w_d = (const float*)d_in[14];
    const float* b_d = (const float*)d_in[15];
    float* out = (float*)d_out;

    cudaFuncSetAttribute(gemm_mma, cudaFuncAttributeMaxDynamicSharedMemorySize, GS_BYTES);

    float *qb, *kb, *vb, *cp;
    bf16 *ah,*al,*qh,*ql,*ffh,*ffl,*kTh,*kTl,*vTh,*vTl,*cTh,*cTl;
    bf16 *WQh,*WQl,*WKh,*WKl,*WVh,*WVl,*WOh,*WOl,*WDh,*WDl,*F1h,*F1l,*F2h,*F2l;
    cudaGetSymbolAddress((void**)&qb, g_q);
    cudaGetSymbolAddress((void**)&kb, g_k);
    cudaGetSymbolAddress((void**)&vb, g_v);
    cudaGetSymbolAddress((void**)&cp, g_cpart);
    cudaGetSymbolAddress((void**)&ah, g_ah);   cudaGetSymbolAddress((void**)&al, g_al);
    cudaGetSymbolAddress((void**)&qh, g_qh);   cudaGetSymbolAddress((void**)&ql, g_ql);
    cudaGetSymbolAddress((void**)&ffh, g_ffh); cudaGetSymbolAddress((void**)&ffl, g_ffl);
    cudaGetSymbolAddress((void**)&kTh, g_kTh); cudaGetSymbolAddress((void**)&kTl, g_kTl);
    cudaGetSymbolAddress((void**)&vTh, g_vTh); cudaGetSymbolAddress((void**)&vTl, g_vTl);
    cudaGetSymbolAddress((void**)&cTh, g_cTh); cudaGetSymbolAddress((void**)&cTl, g_cTl);
    cudaGetSymbolAddress((void**)&WQh, g_wq_hi); cudaGetSymbolAddress((void**)&WQl, g_wq_lo);
    cudaGetSymbolAddress((void**)&WKh, g_wk_hi); cudaGetSymbolAddress((void**)&WKl, g_wk_lo);
    cudaGetSymbolAddress((void**)&WVh, g_wv_hi); cudaGetSymbolAddress((void**)&WVl, g_wv_lo);
    cudaGetSymbolAddress((void**)&WOh, g_wo_hi); cudaGetSymbolAddress((void**)&WOl, g_wo_lo);
    cudaGetSymbolAddress((void**)&WDh, g_wd_hi); cudaGetSymbolAddress((void**)&WDl, g_wd_lo);
    cudaGetSymbolAddress((void**)&F1h, g_f1_hi); cudaGetSymbolAddress((void**)&F1l, g_f1_lo);
    cudaGetSymbolAddress((void**)&F2h, g_f2_hi); cudaGetSymbolAddress((void**)&F2l, g_f2_lo);

    dim3 tb(32, 8);
    wsplit_t<<<dim3(D_/32, D_/32), tb>>>(wq, WQh, WQl, D_, D_);
    wsplit_t<<<dim3(D_/32, D_/32), tb>>>(wk, WKh, WKl, D_, D_);
    wsplit_t<<<dim3(D_/32, D_/32), tb>>>(wv, WVh, WVl, D_, D_);
    wsplit_t<<<dim3(D_/32, D_/32), tb>>>(wo, WOh, WOl, D_, D_);
    wsplit_t<<<dim3(D_/32, D_/32), tb>>>(w_d, WDh, WDl, D_, D_);
    wsplit_t<<<dim3(FF_/32, D_/32), tb>>>(w_ff1, F1h, F1l, D_, FF_);
    wsplit_t<<<dim3(D_/32, FF_/32), tb>>>(w_ff2, F2h, F2l, FF_, D_);

    // 1) LN1 -> split
    layernorm_split<<<ROWS_, 256>>>(x, ln1_g, ln1_b, ah, al);

    // 2) q,k,v projections (f32 out)
    dim3 g1(D_/256, ROWS_/128, 1);
    gemm_mma<<<g1, 256, GS_BYTES>>>(ah, al, WQh, WQl, qb, 0, 0, 0, 0,
                                    D_, D_, D_, 0, 0,0,0,0,0,0,0);
    gemm_mma<<<g1, 256, GS_BYTES>>>(ah, al, WKh, WKl, kb, 0, 0, 0, 0,
                                    D_, D_, D_, 0, 0,0,0,0,0,0,0);
    gemm_mma<<<g1, 256, GS_BYTES>>>(ah, al, WVh, WVl, vb, 0, 0, 0, 0,
                                    D_, D_, D_, 0, 0,0,0,0,0,0,0);

    // 3) feature maps
    softmax_q_split<<<ROWS_*H_/8, 256>>>(qb, qh, ql);
    softmax_k<<<dim3(DH_/32, B_*H_), tb>>>(kb);

    // 4) transpose+split -> [z][d][n]
    trans_split<<<dim3(N_/32, DH_/32, B_*H_), tb>>>(kb, kTh, kTl);
    trans_split<<<dim3(N_/32, DH_/32, B_*H_), tb>>>(vb, vTh, vTl);

    // 5) ctx split-K: part[j][z][e][d] = vT[e][nj] * kT[d][nj]; then reduce+split
    gemm_mma<<<dim3(1, DH_/128, B_*H_*8), 256, GS_BYTES>>>(
        vTh, vTl, kTh, kTl, cp, 0, 0, 0, 0,
        512, N_, DH_, 0,
        8, (long)DH_*N_, 512L, (long)DH_*N_, 512L,
        (long)DH_*DH_, (long)CTXE_);
    reduce_split<<<(CTXE_+255)/256, 256>>>(cp, cTh, cTl);

    // 6) attn = q @ cT^T -> split ah/al [b,n,D]
    gemm_mma<<<dim3(1, N_/128, B_*H_), 256, GS_BYTES>>>(
        qh, ql, cTh, cTl, 0, ah, al, 0, 0,
        DH_, D_, D_, 0,
        H_, (long)N_*D_, (long)DH_, (long)H_*DH_*DH_, (long)DH_*DH_,
        (long)N_*D_, (long)DH_);

    // 7) out1 = x + attn @ wo + bo -> vb (f32)
    gemm_mma<<<g1, 256, GS_BYTES>>>(ah, al, WOh, WOl, vb, 0, 0, bo, x,
                                    D_, D_, D_, 2, 0,0,0,0,0,0,0);

    // 8) LN2 -> split
    layernorm_split<<<ROWS_, 256>>>(vb, ln2_g, ln2_b, ah, al);

    // 9) ff = gelu(h @ w_ff1 + b1) -> split
    gemm_mma<<<dim3(FF_/256, ROWS_/128, 1), 256, GS_BYTES>>>(
        ah, al, F1h, F1l, 0, ffh, ffl, b_ff1, 0,
        D_, D_, FF_, 3, 0,0,0,0,0,0,0);

    // 10) out2 = out1 + ff @ w_ff2 + b2 -> split
    gemm_mma<<<g1, 256, GS_BYTES>>>(ffh, ffl, F2h, F2l, 0, qh, ql, b_ff2, vb,
                                    FF_, FF_, D_, 2, 0,0,0,0,0,0,0);

    // 11) out = out2 @ w_d + b_d (f32)
    gemm_mma<<<g1, 256, GS_BYTES>>>(qh, ql, WDh, WDl, out, 0, 0, b_d, 0,
                                    D_, D_, D_, 1, 0,0,0,0,0,0,0);
}

// round 10
// speedup vs baseline: 1.0504x; 1.0193x over previous
#include <cuda_runtime.h>
#include <cuda_fp16.h>
#include <cstdint>

#define B_ 4
#define N_ 4096
#define D_ 1024
#define H_ 4
#define DH_ 256
#define FF_ 4096
#define ROWS_ (B_*N_)
#define CTXE_ (B_*H_*DH_*DH_)

typedef __half hf;

// ---------------- scratch ----------------
__device__ float g_q[ROWS_*D_];
__device__ float g_k[ROWS_*D_];
__device__ float g_v[ROWS_*D_];
__device__ float g_cpart[8*CTXE_];
__device__ hf g_ah[ROWS_*D_],  g_al[ROWS_*D_];
__device__ hf g_qh[ROWS_*D_],  g_ql[ROWS_*D_];
__device__ hf g_ffh[ROWS_*FF_], g_ffl[ROWS_*FF_];
__device__ hf g_kTh[B_*H_*DH_*N_], g_kTl[B_*H_*DH_*N_];
__device__ hf g_vTh[B_*H_*DH_*N_], g_vTl[B_*H_*DH_*N_];
__device__ hf g_cTh[CTXE_], g_cTl[CTXE_];
__device__ hf g_wq_hi[D_*D_], g_wq_lo[D_*D_], g_wk_hi[D_*D_], g_wk_lo[D_*D_];
__device__ hf g_wv_hi[D_*D_], g_wv_lo[D_*D_], g_wo_hi[D_*D_], g_wo_lo[D_*D_];
__device__ hf g_wd_hi[D_*D_], g_wd_lo[D_*D_];
__device__ hf g_f1_hi[D_*FF_], g_f1_lo[D_*FF_];
__device__ hf g_f2_hi[FF_*D_], g_f2_lo[FF_*D_];

// ---------------- helpers ----------------
__device__ __forceinline__ uint32_t smem_u32(const void* p) {
    uint32_t a;
    asm("{ .reg .u64 t; cvta.to.shared.u64 t, %1; cvt.u32.u64 %0, t; }" : "=r"(a) : "l"(p));
    return a;
}
__device__ __forceinline__ void cp_async16(uint32_t s, const void* g) {
    asm volatile("cp.async.cg.shared.global [%0], [%1], 16;\n" :: "r"(s), "l"(g));
}
__device__ __forceinline__ void cp_commit() { asm volatile("cp.async.commit_group;\n"); }
__device__ __forceinline__ void cp_wait2()  { asm volatile("cp.async.wait_group 2;\n"); }
__device__ __forceinline__ void cp_wait1()  { asm volatile("cp.async.wait_group 1;\n"); }
__device__ __forceinline__ void cp_wait0()  { asm volatile("cp.async.wait_group 0;\n"); }
__device__ __forceinline__ void ldsm4(uint32_t* r, uint32_t a) {
    asm volatile("ldmatrix.sync.aligned.m8n8.x4.shared.b16 {%0,%1,%2,%3}, [%4];"
                 : "=r"(r[0]), "=r"(r[1]), "=r"(r[2]), "=r"(r[3]) : "r"(a));
}
__device__ __forceinline__ void mma16816(float* d, const uint32_t* a, const uint32_t* b) {
    asm volatile(
        "mma.sync.aligned.m16n8k16.row.col.f32.f16.f16.f32 "
        "{%0,%1,%2,%3}, {%4,%5,%6,%7}, {%8,%9}, {%0,%1,%2,%3};"
        : "+f"(d[0]), "+f"(d[1]), "+f"(d[2]), "+f"(d[3])
        : "r"(a[0]), "r"(a[1]), "r"(a[2]), "r"(a[3]), "r"(b[0]), "r"(b[1]));
}
__device__ __forceinline__ float gelu_f(float x) {
    float t = tanhf(0.7978845608028654f * (x + 0.044715f * x * x * x));
    return 0.5f * x * (1.0f + t);
}
__device__ __forceinline__ void split1(float v, hf& h, hf& l) {
    h = __float2half_rn(v);
    l = __float2half_rn(v - __half2float(h));
}
__device__ __forceinline__ uint32_t packhf(hf a, hf b) {
    return ((uint32_t)__half_as_ushort(b) << 16) | __half_as_ushort(a);
}

// ---------------------------------------------------------------------------
// gemm_mma: C[M][Nc] = (Ah+Al)[M][K] @ (Bh+Bl)[Nc][K]^T  3-pass fp16, fp32 acc.
// CTA 128x256, BK=32, 3-stage cp.async, 16 warps (4m x 4n), warp 32x64.
// epi: 0 none, 1 +bias, 2 +bias+resid, 3 gelu(bias+). Chi!=0 -> split output.
// ---------------------------------------------------------------------------
#define LDS_ 40
#define STG_ 61440
#define GS_BYTES (3*STG_)

__global__ void __launch_bounds__(512, 1) gemm_mma(
    const hf* __restrict__ Ah, const hf* __restrict__ Al,
    const hf* __restrict__ Bh, const hf* __restrict__ Bl,
    float* __restrict__ Cf, hf* __restrict__ Chi, hf* __restrict__ Clo,
    const float* __restrict__ bias, const float* __restrict__ resid,
    int K, int lda, int ldc, int epi,
    int bm, long aO, long aI, long bO, long bI, long cO, long cI)
{
    extern __shared__ char smem[];
    uint32_t sb = smem_u32(smem);
    if (bm) {
        int z = blockIdx.z; long o = z / bm, ii = z % bm;
        Ah += o * aO + ii * aI; Al += o * aO + ii * aI;
        Bh += o * bO + ii * bI; Bl += o * bO + ii * bI;
        long co = o * cO + ii * cI;
        if (Cf) Cf += co;
        if (Chi) { Chi += co; Clo += co; }
        if (resid) resid += co;
    }
    int tid = threadIdx.x, lane = tid & 31, wid = tid >> 5;
    int wm = wid >> 2, wn = wid & 3;
    long rowBlk = (long)blockIdx.y * 128;
    int  colBlk = blockIdx.x * 256;

    float acc[2][8][4];
    #pragma unroll
    for (int i = 0; i < 2; i++)
        #pragma unroll
        for (int j = 0; j < 8; j++)
            #pragma unroll
            for (int r = 0; r < 4; r++) acc[i][j][r] = 0.f;

    int ar = tid >> 2, ac = (tid & 3) * 8;   // 512 threads: 1 chunk each for A-hi
    int S = K >> 5;

    #define LOADSTAGE(s) do { \
        long k0 = (long)(s) * 32; \
        uint32_t st = sb + ((s) % 3) * STG_; \
        uint32_t dA = st + (ar * LDS_ + ac) * 2; \
        cp_async16(dA,         Ah + (rowBlk + ar) * lda + k0 + ac); \
        cp_async16(dA + 10240, Al + (rowBlk + ar) * lda + k0 + ac); \
        uint32_t dB0 = st + 20480 + (ar * LDS_ + ac) * 2; \
        uint32_t dB1 = st + 20480 + ((ar + 128) * LDS_ + ac) * 2; \
        cp_async16(dB0,         Bh + (long)(colBlk + ar) * K + k0 + ac); \
        cp_async16(dB1,         Bh + (long)(colBlk + ar + 128) * K + k0 + ac); \
        cp_async16(dB0 + 20480, Bl + (long)(colBlk + ar) * K + k0 + ac); \
        cp_async16(dB1 + 20480, Bl + (long)(colBlk + ar + 128) * K + k0 + ac); \
    } while (0)

    LOADSTAGE(0); cp_commit();
    LOADSTAGE(1); cp_commit();

    int la = lane & 15, lha = (lane >> 4) * 8;
    int brr = ((lane >> 4) & 1) * 8 + (lane & 7);
    int bcc = ((lane >> 3) & 1) * 8;

    for (int s = 0; s < S; s++) {
        if (s + 2 < S) { LOADSTAGE(s + 2); cp_commit(); cp_wait2(); }
        else if (s + 1 < S) cp_wait1();
        else cp_wait0();
        __syncthreads();

        uint32_t st  = sb + (s % 3) * STG_;
        uint32_t sAl = st + 10240, sBh = st + 20480, sBl = st + 40960;

        #pragma unroll
        for (int h = 0; h < 32; h += 16) {
            uint32_t ah0[4], ah1[4], al0[4], al1[4];
            uint32_t ra0 = ((wm * 32 + la) * LDS_ + h + lha) * 2;
            uint32_t ra1 = ((wm * 32 + 16 + la) * LDS_ + h + lha) * 2;
            ldsm4(ah0, st + ra0);
            ldsm4(ah1, st + ra1);
            ldsm4(al0, sAl + ra0);
            ldsm4(al1, sAl + ra1);
            #pragma unroll
            for (int nc = 0; nc < 4; nc++) {
                uint32_t bh[4], bl[4];
                uint32_t rb = ((wn * 64 + nc * 16 + brr) * LDS_ + h + bcc) * 2;
                ldsm4(bh, sBh + rb);
                ldsm4(bl, sBl + rb);
                #pragma unroll
                for (int half = 0; half < 2; half++) {
                    float* a0 = acc[0][nc * 2 + half];
                    float* a1 = acc[1][nc * 2 + half];
                    mma16816(a0, ah0, &bh[half * 2]);
                    mma16816(a1, ah1, &bh[half * 2]);
                    mma16816(a0, ah0, &bl[half * 2]);
                    mma16816(a1, ah1, &bl[half * 2]);
                    mma16816(a0, al0, &bh[half * 2]);
                    mma16816(a1, al1, &bh[half * 2]);
                }
            }
        }
        __syncthreads();
    }

    // epilogue: warp region rows wm*32 + {0,16}, cols wn*64 + nt*8
    int g = lane >> 2, c2 = (lane & 3) * 2;
    #pragma unroll
    for (int mt = 0; mt < 2; mt++) {
        #pragma unroll
        for (int nt = 0; nt < 8; nt++) {
            long rr0 = rowBlk + wm * 32 + mt * 16 + g;
            int  cc  = colBlk + wn * 64 + nt * 8 + c2;
            float2 v0 = make_float2(acc[mt][nt][0], acc[mt][nt][1]);
            float2 v1 = make_float2(acc[mt][nt][2], acc[mt][nt][3]);
            if (epi) {
                float2 bv = *(const float2*)(bias + cc);
                v0.x += bv.x; v0.y += bv.y; v1.x += bv.x; v1.y += bv.y;
            }
            if (epi == 2) {
                float2 q0 = *(const float2*)(resid + rr0 * ldc + cc);
                float2 q1 = *(const float2*)(resid + (rr0 + 8) * ldc + cc);
                v0.x += q0.x; v0.y += q0.y; v1.x += q1.x; v1.y += q1.y;
            }
            if (epi == 3) {
                v0.x = gelu_f(v0.x); v0.y = gelu_f(v0.y);
                v1.x = gelu_f(v1.x); v1.y = gelu_f(v1.y);
            }
            if (Chi) {
                hf h0,l0,h1,l1,h2,l2,h3,l3;
                split1(v0.x,h0,l0); split1(v0.y,h1,l1);
                split1(v1.x,h2,l2); split1(v1.y,h3,l3);
                *(uint32_t*)(Chi + rr0 * ldc + cc)       = packhf(h0, h1);
                *(uint32_t*)(Clo + rr0 * ldc + cc)       = packhf(l0, l1);
                *(uint32_t*)(Chi + (rr0 + 8) * ldc + cc) = packhf(h2, h3);
                *(uint32_t*)(Clo + (rr0 + 8) * ldc + cc) = packhf(l2, l3);
            } else {
                *(float2*)(Cf + rr0 * ldc + cc) = v0;
                *(float2*)(Cf + (rr0 + 8) * ldc + cc) = v1;
            }
        }
    }
}

// ---------------- pointwise kernels ----------------
__global__ void __launch_bounds__(256) layernorm_split(
    const float* __restrict__ x, const float* __restrict__ g,
    const float* __restrict__ b, hf* __restrict__ oh, hf* __restrict__ ol)
{
    long row = blockIdx.x; int t = threadIdx.x;
    float4 v = ((const float4*)(x + row * D_))[t];
    float s = v.x+v.y+v.z+v.w, ss = v.x*v.x+v.y*v.y+v.z*v.z+v.w*v.w;
    #pragma unroll
    for (int o = 16; o; o >>= 1) {
        s += __shfl_xor_sync(~0u, s, o); ss += __shfl_xor_sync(~0u, ss, o);
    }
    __shared__ float shs[8], shss[8], shmu, shrs;
    int w = t >> 5, l = t & 31;
    if (l == 0) { shs[w] = s; shss[w] = ss; }
    __syncthreads();
    if (t == 0) {
        float S = 0, SS = 0;
        #pragma unroll
        for (int i = 0; i < 8; i++) { S += shs[i]; SS += shss[i]; }
        float mu = S / D_;
        shmu = mu; shrs = rsqrtf(SS / D_ - mu * mu + 1e-5f);
    }
    __syncthreads();
    float mu = shmu, rs = shrs;
    float4 gg = ((const float4*)g)[t], bb = ((const float4*)b)[t];
    float o0 = (v.x-mu)*rs*gg.x+bb.x, o1 = (v.y-mu)*rs*gg.y+bb.y;
    float o2 = (v.z-mu)*rs*gg.z+bb.z, o3 = (v.w-mu)*rs*gg.w+bb.w;
    hf h0,l0,h1,l1,h2,l2,h3,l3;
    split1(o0,h0,l0); split1(o1,h1,l1); split1(o2,h2,l2); split1(o3,h3,l3);
    *(uint2*)(oh + row * D_ + t*4) = make_uint2(packhf(h0,h1), packhf(h2,h3));
    *(uint2*)(ol + row * D_ + t*4) = make_uint2(packhf(l0,l1), packhf(l2,l3));
}

__global__ void __launch_bounds__(256) softmax_q_split(
    const float* __restrict__ q, hf* __restrict__ qh, hf* __restrict__ ql)
{
    int warp = threadIdx.x >> 5, lane = threadIdx.x & 31;
    long row = (long)blockIdx.x * 8 + warp;
    const float* p = q + row * DH_;
    float v[8], mx = -1e30f;
    #pragma unroll
    for (int i = 0; i < 8; i++) { v[i] = p[lane + i*32] * 0.25f; mx = fmaxf(mx, v[i]); }
    #pragma unroll
    for (int o = 16; o; o >>= 1) mx = fmaxf(mx, __shfl_xor_sync(~0u, mx, o));
    float s = 0.f;
    #pragma unroll
    for (int i = 0; i < 8; i++) { v[i] = expf(v[i] - mx); s += v[i]; }
    #pragma unroll
    for (int o = 16; o; o >>= 1) s += __shfl_xor_sync(~0u, s, o);
    float inv = 1.f / s;
    #pragma unroll
    for (int i = 0; i < 8; i++) {
        hf h, l; split1(v[i] * inv, h, l);
        qh[row * DH_ + lane + i*32] = h;
        ql[row * DH_ + lane + i*32] = l;
    }
}

__global__ void softmax_k(float* __restrict__ k)
{
    int b = blockIdx.y >> 2, h = blockIdx.y & 3;
    float* base = k + (long)b*N_*D_ + h*DH_ + blockIdx.x*32 + threadIdx.x;
    __shared__ float red[8][32];
    int tx = threadIdx.x, ty = threadIdx.y;
    float mx = -1e30f;
    for (int n = ty; n < N_; n += 8) mx = fmaxf(mx, base[(long)n * D_]);
    red[ty][tx] = mx; __syncthreads();
    #pragma unroll
    for (int i = 0; i < 8; i++) mx = fmaxf(mx, red[i][tx]);
    mx *= 0.25f; __syncthreads();
    float s = 0.f;
    for (int n = ty; n < N_; n += 8) s += expf(base[(long)n * D_] * 0.25f - mx);
    red[ty][tx] = s; __syncthreads();
    s = 0.f;
    #pragma unroll
    for (int i = 0; i < 8; i++) s += red[i][tx];
    float inv = 1.f / s;
    for (int n = ty; n < N_; n += 8)
        base[(long)n * D_] = expf(base[(long)n * D_] * 0.25f - mx) * inv;
}

__global__ void wsplit_t(const float* __restrict__ W, hf* __restrict__ hi,
                         hf* __restrict__ lo, int K, int Nc)
{
    __shared__ float t[32][33];
    int k0 = blockIdx.y*32, n0 = blockIdx.x*32, tx = threadIdx.x, ty = threadIdx.y;
    #pragma unroll
    for (int i = 0; i < 32; i += 8) t[ty+i][tx] = W[(long)(k0+ty+i)*Nc + n0+tx];
    __syncthreads();
    #pragma unroll
    for (int i = 0; i < 32; i += 8) {
        hf h, l; split1(t[tx][ty+i], h, l);
        long o = (long)(n0+ty+i)*K + k0+tx;
        hi[o] = h; lo[o] = l;
    }
}
__global__ void trans_split(const float* __restrict__ src_, hf* __restrict__ hi,
                            hf* __restrict__ lo)
{
    __shared__ float t[32][33];
    int z = blockIdx.z, b = z >> 2, h = z & 3;
    int n0 = blockIdx.x*32, d0 = blockIdx.y*32, tx = threadIdx.x, ty = threadIdx.y;
    const float* src = src_ + (long)b*N_*D_ + h*DH_;
    #pragma unroll
    for (int i = 0; i < 32; i += 8) t[ty+i][tx] = src[(long)(n0+ty+i)*D_ + d0+tx];
    __syncthreads();
    long base = (long)z*DH_*N_;
    #pragma unroll
    for (int i = 0; i < 32; i += 8) {
        hf hh, ll; split1(t[tx][ty+i], hh, ll);
        long o = base + (long)(d0+ty+i)*N_ + n0+tx;
        hi[o] = hh; lo[o] = ll;
    }
}
__global__ void reduce_split(const float* __restrict__ part,
                             hf* __restrict__ hi, hf* __restrict__ lo)
{
    int i = blockIdx.x * 256 + threadIdx.x;
    if (i < CTXE_) {
        float s = 0.f;
        #pragma unroll
        for (int j = 0; j < 8; j++) s += part[(long)j * CTXE_ + i];
        hf h, l; split1(s, h, l);
        hi[i] = h; lo[i] = l;
    }
}

// ---------------------------------------------------------------------------
extern "C" void kernel_launch(void* const* d_in, const int* in_sizes, int n_in,
                              void* d_out, int out_size)
{
    const float* x     = (const float*)d_in[0];
    const float* ln1_g = (const float*)d_in[1];
    const float* ln1_b = (const float*)d_in[2];
    const float* wq = (const float*)d_in[3];
    const float* wk = (const float*)d_in[4];
    const float* wv = (const float*)d_in[5];
    const float* wo = (const float*)d_in[6];
    const float* bo = (const float*)d_in[7];
    const float* ln2_g = (const float*)d_in[8];
    const float* ln2_b = (const float*)d_in[9];
    const float* w_ff1 = (const float*)d_in[10];
    const float* b_ff1 = (const float*)d_in[11];
    const float* w_ff2 = (const float*)d_in[12];
    const float* b_ff2 = (const float*)d_in[13];
    const float* w_d = (const float*)d_in[14];
    const float* b_d = (const float*)d_in[15];
    float* out = (float*)d_out;

    cudaFuncSetAttribute(gemm_mma, cudaFuncAttributeMaxDynamicSharedMemorySize, GS_BYTES);

    float *qb, *kb, *vb, *cp;
    hf *ah,*al,*qh,*ql,*ffh,*ffl,*kTh,*kTl,*vTh,*vTl,*cTh,*cTl;
    hf *WQh,*WQl,*WKh,*WKl,*WVh,*WVl,*WOh,*WOl,*WDh,*WDl,*F1h,*F1l,*F2h,*F2l;
    cudaGetSymbolAddress((void**)&qb, g_q);
    cudaGetSymbolAddress((void**)&kb, g_k);
    cudaGetSymbolAddress((void**)&vb, g_v);
    cudaGetSymbolAddress((void**)&cp, g_cpart);
    cudaGetSymbolAddress((void**)&ah, g_ah);   cudaGetSymbolAddress((void**)&al, g_al);
    cudaGetSymbolAddress((void**)&qh, g_qh);   cudaGetSymbolAddress((void**)&ql, g_ql);
    cudaGetSymbolAddress((void**)&ffh, g_ffh); cudaGetSymbolAddress((void**)&ffl, g_ffl);
    cudaGetSymbolAddress((void**)&kTh, g_kTh); cudaGetSymbolAddress((void**)&kTl, g_kTl);
    cudaGetSymbolAddress((void**)&vTh, g_vTh); cudaGetSymbolAddress((void**)&vTl, g_vTl);
    cudaGetSymbolAddress((void**)&cTh, g_cTh); cudaGetSymbolAddress((void**)&cTl, g_cTl);
    cudaGetSymbolAddress((void**)&WQh, g_wq_hi); cudaGetSymbolAddress((void**)&WQl, g_wq_lo);
    cudaGetSymbolAddress((void**)&WKh, g_wk_hi); cudaGetSymbolAddress((void**)&WKl, g_wk_lo);
    cudaGetSymbolAddress((void**)&WVh, g_wv_hi); cudaGetSymbolAddress((void**)&WVl, g_wv_lo);
    cudaGetSymbolAddress((void**)&WOh, g_wo_hi); cudaGetSymbolAddress((void**)&WOl, g_wo_lo);
    cudaGetSymbolAddress((void**)&WDh, g_wd_hi); cudaGetSymbolAddress((void**)&WDl, g_wd_lo);
    cudaGetSymbolAddress((void**)&F1h, g_f1_hi); cudaGetSymbolAddress((void**)&F1l, g_f1_lo);
    cudaGetSymbolAddress((void**)&F2h, g_f2_hi); cudaGetSymbolAddress((void**)&F2l, g_f2_lo);

    dim3 tb(32, 8);
    wsplit_t<<<dim3(D_/32, D_/32), tb>>>(wq, WQh, WQl, D_, D_);
    wsplit_t<<<dim3(D_/32, D_/32), tb>>>(wk, WKh, WKl, D_, D_);
    wsplit_t<<<dim3(D_/32, D_/32), tb>>>(wv, WVh, WVl, D_, D_);
    wsplit_t<<<dim3(D_/32, D_/32), tb>>>(wo, WOh, WOl, D_, D_);
    wsplit_t<<<dim3(D_/32, D_/32), tb>>>(w_d, WDh, WDl, D_, D_);
    wsplit_t<<<dim3(FF_/32, D_/32), tb>>>(w_ff1, F1h, F1l, D_, FF_);
    wsplit_t<<<dim3(D_/32, FF_/32), tb>>>(w_ff2, F2h, F2l, FF_, D_);

    // 1) LN1 -> split
    layernorm_split<<<ROWS_, 256>>>(x, ln1_g, ln1_b, ah, al);

    // 2) q,k,v projections (f32 out)
    dim3 g1(D_/256, ROWS_/128, 1);
    gemm_mma<<<g1, 512, GS_BYTES>>>(ah, al, WQh, WQl, qb, 0, 0, 0, 0,
                                    D_, D_, D_, 0, 0,0,0,0,0,0,0);
    gemm_mma<<<g1, 512, GS_BYTES>>>(ah, al, WKh, WKl, kb, 0, 0, 0, 0,
                                    D_, D_, D_, 0, 0,0,0,0,0,0,0);
    gemm_mma<<<g1, 512, GS_BYTES>>>(ah, al, WVh, WVl, vb, 0, 0, 0, 0,
                                    D_, D_, D_, 0, 0,0,0,0,0,0,0);

    // 3) feature maps
    softmax_q_split<<<ROWS_*H_/8, 256>>>(qb, qh, ql);
    softmax_k<<<dim3(DH_/32, B_*H_), tb>>>(kb);

    // 4) transpose+split -> [z][d][n]
    trans_split<<<dim3(N_/32, DH_/32, B_*H_), tb>>>(kb, kTh, kTl);
    trans_split<<<dim3(N_/32, DH_/32, B_*H_), tb>>>(vb, vTh, vTl);

    // 5) ctx split-K: part[j][z][e][d]; then reduce+split
    gemm_mma<<<dim3(1, DH_/128, B_*H_*8), 512, GS_BYTES>>>(
        vTh, vTl, kTh, kTl, cp, 0, 0, 0, 0,
        512, N_, DH_, 0,
        8, (long)DH_*N_, 512L, (long)DH_*N_, 512L,
        (long)DH_*DH_, (long)CTXE_);
    reduce_split<<<(CTXE_+255)/256, 256>>>(cp, cTh, cTl);

    // 6) attn = q @ cT^T -> split ah/al [b,n,D]
    gemm_mma<<<dim3(1, N_/128, B_*H_), 512, GS_BYTES>>>(
        qh, ql, cTh, cTl, 0, ah, al, 0, 0,
        DH_, D_, D_, 0,
        H_, (long)N_*D_, (long)DH_, (long)H_*DH_*DH_, (long)DH_*DH_,
        (long)N_*D_, (long)DH_);

    // 7) out1 = x + attn @ wo + bo -> vb (f32)
    gemm_mma<<<g1, 512, GS_BYTES>>>(ah, al, WOh, WOl, vb, 0, 0, bo, x,
                                    D_, D_, D_, 2, 0,0,0,0,0,0,0);

    // 8) LN2 -> split
    layernorm_split<<<ROWS_, 256>>>(vb, ln2_g, ln2_b, ah, al);

    // 9) ff = gelu(h @ w_ff1 + b1) -> split
    gemm_mma<<<dim3(FF_/256, ROWS_/128, 1), 512, GS_BYTES>>>(
        ah, al, F1h, F1l, 0, ffh, ffl, b_ff1, 0,
        D_, D_, FF_, 3, 0,0,0,0,0,0,0);

    // 10) out2 = out1 + ff @ w_ff2 + b2 -> split
    gemm_mma<<<g1, 512, GS_BYTES>>>(ffh, ffl, F2h, F2l, 0, qh, ql, b_ff2, vb,
                                    FF_, FF_, D_, 2, 0,0,0,0,0,0,0);

    // 11) out = out2 @ w_d + b_d (f32)
    gemm_mma<<<g1, 512, GS_BYTES>>>(qh, ql, WDh, WDl, out, 0, 0, b_d, 0,
                                    D_, D_, D_, 1, 0,0,0,0,0,0,0);
}